// round 2
// baseline (speedup 1.0000x reference)
#include <cuda_runtime.h>
#include <cuda_fp16.h>
#include <cstdint>

#define NV 65536
#define KK 27
#define CH 128

// Select tcgen05 fast path only when compiling for the arch-specific sm_103a
// target (the plain compute_103 pass rejects tcgen05 in ptxas).
#if defined(__CUDA_ARCH__) && (defined(__CUDA_ARCH_FEAT_SM103_ALL) || \
    (defined(__CUDA_ARCH_SPECIFIC__) && (__CUDA_ARCH_SPECIFIC__ == 1030)))
#define TC_PATH 1
#else
#define TC_PATH 0
#endif

// ---------------- scratch (static __device__, no allocs) ----------------
__device__ __align__(256) int    g_nbr[KK * NV];            // 7 MB
__device__ __align__(256) __half g_f16[(NV + 1) * CH];      // 16.8 MB (+zero row)
__device__ __align__(256) __half g_w16[KK * CH * CH];       // 864 KB, layout depends on path

// ---------------- common helpers ----------------
__device__ __forceinline__ uint32_t smem_to_u32(const void* smem_ptr) {
    uint32_t addr;
    asm("{ .reg .u64 tmp; cvta.to.shared.u64 tmp, %1; cvt.u32.u64 %0, tmp; }"
        : "=r"(addr) : "l"(smem_ptr));
    return addr;
}

#if TC_PATH
// ---------------- tcgen05 helpers (only in sm_103a pass) ----------------
__device__ __forceinline__ uint32_t elect_one_pred() {
    uint32_t pred;
    asm volatile(
        "{\n\t.reg .pred p;\n\t"
        "elect.sync _|p, 0xFFFFFFFF;\n\t"
        "selp.b32 %0, 1, 0, p;\n\t}"
        : "=r"(pred));
    return pred;
}

#define TCGEN05_ALLOC(smem_result_addr, nCols) \
    asm volatile("tcgen05.alloc.cta_group::1.sync.aligned.shared::cta.b32 [%0], %1;" \
                 :: "r"((uint32_t)(smem_result_addr)), "r"((uint32_t)(nCols)) : "memory")
#define TCGEN05_DEALLOC(tmem_addr, nCols) \
    asm volatile("tcgen05.dealloc.cta_group::1.sync.aligned.b32 %0, %1;" \
                 :: "r"(tmem_addr), "r"((uint32_t)(nCols)))
#define TCGEN05_RELINQUISH_ALLOC_PERMIT() \
    asm volatile("tcgen05.relinquish_alloc_permit.cta_group::1.sync.aligned;")
#define TCGEN05_WAIT_ST() asm volatile("tcgen05.wait::st.sync.aligned;" ::: "memory")
#define TCGEN05_WAIT_LD() asm volatile("tcgen05.wait::ld.sync.aligned;" ::: "memory")
#define TCGEN05_FENCE_BEFORE() asm volatile("tcgen05.fence::before_thread_sync;" ::: "memory")
#define TCGEN05_FENCE_AFTER()  asm volatile("tcgen05.fence::after_thread_sync;" ::: "memory")
#define TCGEN05_COMMIT(mbar_smem_addr) \
    asm volatile("tcgen05.commit.cta_group::1.mbarrier::arrive::one.shared::cluster.b64 [%0];" \
                 :: "r"((uint32_t)(mbar_smem_addr)) : "memory")
#define FENCE_PROXY_ASYNC_SHARED_CTA() \
    asm volatile("fence.proxy.async.shared::cta;" ::: "memory")
#define MBARRIER_INIT(mbar_smem_addr, count) \
    asm volatile("mbarrier.init.shared.b64 [%0], %1;" \
                 :: "r"((uint32_t)(mbar_smem_addr)), "r"((uint32_t)(count)) : "memory")
#define MBARRIER_WAIT_PARITY(mbar_smem_addr, phase_parity) do { \
    uint32_t _mbar = (uint32_t)(mbar_smem_addr); \
    uint32_t _parity = (uint32_t)(phase_parity); \
    uint32_t _done; \
    asm volatile( \
        "{\n\t.reg .pred p;\n\t" \
        "mbarrier.try_wait.parity.acquire.cta.shared::cta.b64 p, [%1], %2;\n\t" \
        "selp.b32 %0, 1, 0, p;\n\t}" \
        : "=r"(_done) : "r"(_mbar), "r"(_parity) : "memory"); \
    if (!_done) { \
        asm volatile( \
            "{\n\t.reg .pred P1;\n\t" \
            "WAIT_LOOP_%=:\n\t" \
            "mbarrier.try_wait.parity.acquire.cta.shared::cta.b64 P1, [%0], %1, 0x989680;\n\t" \
            "@P1 bra.uni WAIT_DONE_%=;\n\t" \
            "bra.uni WAIT_LOOP_%=;\n\t" \
            "WAIT_DONE_%=:\n\t}" \
            :: "r"(_mbar), "r"(_parity) : "memory"); \
    } \
} while(0)

#define TCGEN05_MMA_F16(d_tmem, a_tmem, b_smem_desc, idesc, enable_d) do { \
    uint32_t _enable = (enable_d) ? 1 : 0; \
    uint32_t _zero = 0; \
    asm volatile( \
        "{\n\t.reg .pred p;\n\t" \
        "setp.ne.u32 p, %6, 0;\n\t" \
        "tcgen05.mma.cta_group::1.kind::f16 [%0], [%1], %2, %3, " \
        "{%4, %4, %4, %4}, p;\n\t}" \
        :: "r"(d_tmem), "r"(a_tmem), "l"(b_smem_desc), "r"(idesc), \
           "r"(_zero), "r"(_zero), "r"(_enable) \
        : "memory"); \
} while(0)

#define TCGEN05_ST_32X32B_X64(tmem_addr, r) \
    asm volatile( \
        "tcgen05.st.sync.aligned.32x32b.x64.b32 [%0], " \
        "{%1, %2, %3, %4, %5, %6, %7, %8, " \
        " %9, %10, %11, %12, %13, %14, %15, %16, " \
        " %17, %18, %19, %20, %21, %22, %23, %24, " \
        " %25, %26, %27, %28, %29, %30, %31, %32, " \
        " %33, %34, %35, %36, %37, %38, %39, %40, " \
        " %41, %42, %43, %44, %45, %46, %47, %48, " \
        " %49, %50, %51, %52, %53, %54, %55, %56, " \
        " %57, %58, %59, %60, %61, %62, %63, %64};" \
        :: "r"(tmem_addr), \
           "r"((r)[0]),  "r"((r)[1]),  "r"((r)[2]),  "r"((r)[3]), \
           "r"((r)[4]),  "r"((r)[5]),  "r"((r)[6]),  "r"((r)[7]), \
           "r"((r)[8]),  "r"((r)[9]),  "r"((r)[10]), "r"((r)[11]), \
           "r"((r)[12]), "r"((r)[13]), "r"((r)[14]), "r"((r)[15]), \
           "r"((r)[16]), "r"((r)[17]), "r"((r)[18]), "r"((r)[19]), \
           "r"((r)[20]), "r"((r)[21]), "r"((r)[22]), "r"((r)[23]), \
           "r"((r)[24]), "r"((r)[25]), "r"((r)[26]), "r"((r)[27]), \
           "r"((r)[28]), "r"((r)[29]), "r"((r)[30]), "r"((r)[31]), \
           "r"((r)[32]), "r"((r)[33]), "r"((r)[34]), "r"((r)[35]), \
           "r"((r)[36]), "r"((r)[37]), "r"((r)[38]), "r"((r)[39]), \
           "r"((r)[40]), "r"((r)[41]), "r"((r)[42]), "r"((r)[43]), \
           "r"((r)[44]), "r"((r)[45]), "r"((r)[46]), "r"((r)[47]), \
           "r"((r)[48]), "r"((r)[49]), "r"((r)[50]), "r"((r)[51]), \
           "r"((r)[52]), "r"((r)[53]), "r"((r)[54]), "r"((r)[55]), \
           "r"((r)[56]), "r"((r)[57]), "r"((r)[58]), "r"((r)[59]), \
           "r"((r)[60]), "r"((r)[61]), "r"((r)[62]), "r"((r)[63]) \
        : "memory")

#define TCGEN05_LD_32X32B_X32(r, tmem_addr) \
    asm volatile( \
        "tcgen05.ld.sync.aligned.32x32b.x32.b32 " \
        "{%0, %1, %2, %3, %4, %5, %6, %7, " \
        " %8, %9, %10, %11, %12, %13, %14, %15, " \
        " %16, %17, %18, %19, %20, %21, %22, %23, " \
        " %24, %25, %26, %27, %28, %29, %30, %31}, [%32];" \
        : "=r"((r)[0]),  "=r"((r)[1]),  "=r"((r)[2]),  "=r"((r)[3]), \
          "=r"((r)[4]),  "=r"((r)[5]),  "=r"((r)[6]),  "=r"((r)[7]), \
          "=r"((r)[8]),  "=r"((r)[9]),  "=r"((r)[10]), "=r"((r)[11]), \
          "=r"((r)[12]), "=r"((r)[13]), "=r"((r)[14]), "=r"((r)[15]), \
          "=r"((r)[16]), "=r"((r)[17]), "=r"((r)[18]), "=r"((r)[19]), \
          "=r"((r)[20]), "=r"((r)[21]), "=r"((r)[22]), "=r"((r)[23]), \
          "=r"((r)[24]), "=r"((r)[25]), "=r"((r)[26]), "=r"((r)[27]), \
          "=r"((r)[28]), "=r"((r)[29]), "=r"((r)[30]), "=r"((r)[31]) \
        : "r"(tmem_addr))

static constexpr uint64_t SMEM_DESC_BASE_SW128 =
    (uint64_t(2) << 61) | (uint64_t(1) << 46) | (uint64_t(64) << 32) | (uint64_t(1) << 16);
#define MAKE_SMEM_DESC(base_addr) \
    (SMEM_DESC_BASE_SW128 | ((uint64_t)((base_addr) >> 4) & 0x3FFF))

// kind::f16, f16 inputs, f32 acc, M=128 (8<<24), N=128 (16<<17)
#define MMA_IDESC_F16 0x8200010u
#endif  // TC_PATH

// ---------------- prep kernels ----------------
__global__ void k_fill() {
    int i = blockIdx.x * blockDim.x + threadIdx.x;
    if (i < KK * NV) g_nbr[i] = NV;   // default: zero row
}

__global__ void k_scatter(const int* __restrict__ in_idx, const int* __restrict__ out_idx) {
    int i = blockIdx.x * blockDim.x + threadIdx.x;
    if (i >= KK * NV) return;
    int o = out_idx[i];
    if (o < NV) g_nbr[(i / NV) * NV + o] = in_idx[i];   // one writer per (k, o)
}

__global__ void k_splitf(const float* __restrict__ f) {
    int i = blockIdx.x * blockDim.x + threadIdx.x;      // half2 word index
    if (i >= (NV + 1) * (CH / 2)) return;
    float2 v = (i < NV * (CH / 2)) ? ((const float2*)f)[i] : make_float2(0.f, 0.f);
    __half2 h;
    h.x = __float2half_rn(v.x);
    h.y = __float2half_rn(v.y);
    ((__half2*)g_f16)[i] = h;
}

// Weight prep. Layout depends on the compiled path (consistent per-arch cubin).
__global__ void k_prepw(const float* __restrict__ w) {
    int i = blockIdx.x * blockDim.x + threadIdx.x;
#if TC_PATH
    // transpose W[k][cin][cout] -> B[k][cout(row)][cin(col)] fp16, SW128 blocked image
    if (i >= KK * CH * CH) return;
    int k = i >> 14;
    int r = (i >> 7) & 127;   // c_out (N row)
    int c = i & 127;          // c_in  (K col)
    float v = w[(k << 14) + (c << 7) + r];
    // atom = 8 rows x 64 fp16 (128B); 16 atom-rows, 2 atom-cols
    uint32_t atom = (uint32_t)(r >> 3) + ((uint32_t)(c >> 6) << 4);
    uint32_t off = atom * 1024u + (uint32_t)(r & 7) * 128u + (uint32_t)(c & 63) * 2u;
    off ^= (off >> 3) & 0x70u;   // SW128 swizzle
    g_w16[((uint32_t)k * 32768u + off) >> 1] = __float2half_rn(v);
#else
    // mma.sync B-fragment-ready image: [k][ktile(8)][ntile(16)][lane(32)][reg(2)] u32
    if (i >= KK * 8 * 16 * 32 * 2) return;
    int reg   = i & 1;
    int lane  = (i >> 1) & 31;
    int nt    = (i >> 6) & 15;
    int ktile = (i >> 10) & 7;
    int k     = i >> 13;
    int tig = lane & 3, gid = lane >> 2;
    int n    = nt * 8 + gid;
    int cin0 = ktile * 16 + tig * 2 + reg * 8;
    float w0 = w[(k * CH + cin0) * CH + n];
    float w1 = w[(k * CH + cin0 + 1) * CH + n];
    __half2 h;
    h.x = __float2half_rn(w0);   // even k -> low half
    h.y = __float2half_rn(w1);
    ((__half2*)g_w16)[i] = h;
#endif
}

// ---------------- main kernel ----------------
#define SMEM_BYTES 131584

#if TC_PATH
// SMEM: [0] tmem ptr, [8],[16] mbar[2], [64..576) bias, [1024..) W stages (32KB each)
// TMEM: D fp32 cols 0..127; A stage s: cols 128 + 64*s .. +64 (fp16 packed 2/col)
#define SM_W(s) (1024u + (uint32_t)(s) * 32768u)

__global__ void __launch_bounds__(256, 1)
k_main(const float* __restrict__ bias, float* __restrict__ out) {
    extern __shared__ char smem[];
    uint32_t sb = smem_to_u32(smem);
    int tid = threadIdx.x;
    int wid = tid >> 5;
    int o0 = blockIdx.x * 128;

    if (wid == 4) TCGEN05_ALLOC(sb + 0, 512);
    if (tid == 0) { MBARRIER_INIT(sb + 8, 1); MBARRIER_INIT(sb + 16, 1); }
    if (tid < 128) ((float*)(smem + 64))[tid] = bias[tid];
    __syncthreads();
    uint32_t tmem;
    asm volatile("ld.shared.b32 %0, [%1];" : "=r"(tmem) : "r"(sb));
    if (wid == 4) TCGEN05_RELINQUISH_ALLOC_PERMIT();

    int pc0 = 0, pc1 = 0;
    for (int k = 0; k < KK; ++k) {
        int s = k & 1;
        if (k >= 2) {  // stage s reusable once MMA k-2 committed
            if (s == 0) { MBARRIER_WAIT_PARITY(sb + 8, pc0); pc0 ^= 1; }
            else        { MBARRIER_WAIT_PARITY(sb + 16, pc1); pc1 ^= 1; }
        }
        if (tid < 128) {
            // WG0: gather one fp16 feature row (or zero row) straight into TMEM
            int nb = __ldg(&g_nbr[k * NV + o0 + tid]);
            uint32_t adst = tmem + 128u + (uint32_t)s * 64u + (((uint32_t)tid >> 5) << 21);
            const uint4* src = (const uint4*)(g_f16 + (size_t)nb * CH);
            uint32_t a[64];
            #pragma unroll
            for (int i = 0; i < 16; ++i) {
                uint4 v = __ldg(src + i);
                a[4*i] = v.x; a[4*i+1] = v.y; a[4*i+2] = v.z; a[4*i+3] = v.w;
            }
            TCGEN05_ST_32X32B_X64(adst, a);
            TCGEN05_WAIT_ST();
            TCGEN05_FENCE_BEFORE();
        } else {
            // WG1: copy pre-swizzled W[k] image (32KB) into stage-s SMEM
            int t = tid - 128;
            const uint4* sh = (const uint4*)((const char*)g_w16 + (size_t)k * 32768);
            uint4* dh = (uint4*)(smem + SM_W(s));
            #pragma unroll
            for (int i = 0; i < 16; ++i) dh[t + i * 128] = __ldg(sh + t + i * 128);
            FENCE_PROXY_ASYNC_SHARED_CTA();
        }
        __syncthreads();
        if (wid == 4) {
            TCGEN05_FENCE_AFTER();
            if (elect_one_pred()) {
                uint32_t ah = tmem + 128u + (uint32_t)s * 64u;
                uint64_t bh = MAKE_SMEM_DESC(sb + SM_W(s));
                #pragma unroll
                for (int ks = 0; ks < 8; ++ks) {
                    // K-step: 16 fp16 = 32B = 2 desc units; atom-col 1 at 16KB = 1024 units
                    uint64_t doff = (ks < 4) ? (uint64_t)(2 * ks)
                                             : (uint64_t)(1024 + 2 * (ks - 4));
                    TCGEN05_MMA_F16(tmem, ah + (uint32_t)ks * 8u, bh + doff, MMA_IDESC_F16,
                                    (k > 0 || ks > 0));
                }
                TCGEN05_COMMIT(sb + 8u + (uint32_t)s * 8u);
            }
        }
    }
    MBARRIER_WAIT_PARITY(sb + 16, pc1);
    MBARRIER_WAIT_PARITY(sb + 8, pc0);
    TCGEN05_FENCE_AFTER();

    if (tid < 128) {
        float* orow = out + (size_t)(o0 + tid) * CH;
        const float* bsm = (const float*)(smem + 64);
        #pragma unroll
        for (int b = 0; b < 128; b += 32) {
            uint32_t d[32];
            TCGEN05_LD_32X32B_X32(d, tmem + (uint32_t)b);
            TCGEN05_WAIT_LD();
            #pragma unroll
            for (int c = 0; c < 32; c += 4) {
                float4 v;
                v.x = __uint_as_float(d[c + 0]) + bsm[b + c + 0];
                v.y = __uint_as_float(d[c + 1]) + bsm[b + c + 1];
                v.z = __uint_as_float(d[c + 2]) + bsm[b + c + 2];
                v.w = __uint_as_float(d[c + 3]) + bsm[b + c + 3];
                *(float4*)(orow + b + c) = v;
            }
        }
    }
    __syncthreads();
    if (wid == 4) TCGEN05_DEALLOC(tmem, 512);
}

#else  // ---------------- mma.sync fallback path ----------------
// SMEM: A stages [s][warp] 4KB each at 0..64KB; W stages 32KB at 64KB..128KB;
// bias at 131072..131584.
#define AW_OFF(s, w) (((s) * 8 + (w)) * 4096)
#define WW_OFF(s)    (65536 + (s) * 32768)
#define BIAS_OFF     131072

__device__ __forceinline__ void mma16816(float* c, uint32_t a0, uint32_t a1,
                                         uint32_t a2, uint32_t a3,
                                         uint32_t b0, uint32_t b1) {
    asm volatile(
        "mma.sync.aligned.m16n8k16.row.col.f32.f16.f16.f32 "
        "{%0,%1,%2,%3}, {%4,%5,%6,%7}, {%8,%9}, {%0,%1,%2,%3};"
        : "+f"(c[0]), "+f"(c[1]), "+f"(c[2]), "+f"(c[3])
        : "r"(a0), "r"(a1), "r"(a2), "r"(a3), "r"(b0), "r"(b1));
}

__global__ void __launch_bounds__(256, 1)
k_main(const float* __restrict__ bias, float* __restrict__ out) {
    extern __shared__ char smem[];
    uint32_t sb = smem_to_u32(smem);
    int tid = threadIdx.x;
    int wid = tid >> 5;
    int lane = tid & 31;
    int o0 = blockIdx.x * 128;

    if (tid < 128) ((float*)(smem + BIAS_OFF))[tid] = __ldg(&bias[tid]);

    float acc[16][4] = {};
    uint4 ra[8], rw[8];

    // --- prologue: load k=0 ---
    {
        int nbl = (lane < 16) ? __ldg(&g_nbr[0 * NV + o0 + wid * 16 + lane]) : 0;
        #pragma unroll
        for (int i = 0; i < 8; ++i) {
            int row = i * 2 + (lane >> 4);
            int rn = __shfl_sync(0xffffffffu, nbl, row);
            ra[i] = __ldg((const uint4*)(g_f16 + (size_t)rn * CH) + (lane & 15));
        }
        const uint4* ws = (const uint4*)((const char*)g_w16) + wid * 256 + lane;
        #pragma unroll
        for (int i = 0; i < 8; ++i) rw[i] = __ldg(ws + i * 32);
        // store stage 0
        char* ab = smem + AW_OFF(0, wid);
        #pragma unroll
        for (int i = 0; i < 8; ++i) {
            int row = i * 2 + (lane >> 4);
            int c = lane & 15;
            *(uint4*)(ab + row * 256 + ((c ^ (row & 7)) << 4)) = ra[i];
        }
        uint4* wd = (uint4*)(smem + WW_OFF(0)) + wid * 256 + lane;
        #pragma unroll
        for (int i = 0; i < 8; ++i) wd[i * 32] = rw[i];
    }
    __syncthreads();

    int m = lane >> 3, rl = lane & 7;
    int lrow = rl + ((m & 1) << 3);

    for (int k = 0; k < KK; ++k) {
        int s = k & 1;
        // issue global loads for k+1 (overlap with MMA below)
        if (k + 1 < KK) {
            int nbl = (lane < 16) ? __ldg(&g_nbr[(k + 1) * NV + o0 + wid * 16 + lane]) : 0;
            #pragma unroll
            for (int i = 0; i < 8; ++i) {
                int row = i * 2 + (lane >> 4);
                int rn = __shfl_sync(0xffffffffu, nbl, row);
                ra[i] = __ldg((const uint4*)(g_f16 + (size_t)rn * CH) + (lane & 15));
            }
            const uint4* ws = (const uint4*)((const char*)g_w16 + (size_t)(k + 1) * 32768)
                              + wid * 256 + lane;
            #pragma unroll
            for (int i = 0; i < 8; ++i) rw[i] = __ldg(ws + i * 32);
        }
        // compute on stage s
        {
            uint32_t ab32 = sb + AW_OFF(s, wid);
            uint32_t wb32 = sb + WW_OFF(s);
            uint32_t arow = ab32 + (uint32_t)lrow * 256u;
            #pragma unroll
            for (int kt = 0; kt < 8; ++kt) {
                int chunk = kt * 2 + (m >> 1);
                uint32_t aaddr = arow + (uint32_t)((chunk ^ (lrow & 7)) << 4);
                uint32_t a0, a1, a2, a3;
                asm volatile(
                    "ldmatrix.sync.aligned.m8n8.x4.shared.b16 {%0,%1,%2,%3}, [%4];"
                    : "=r"(a0), "=r"(a1), "=r"(a2), "=r"(a3) : "r"(aaddr));
                #pragma unroll
                for (int nt = 0; nt < 16; ++nt) {
                    uint32_t baddr = wb32 + (uint32_t)((((kt << 4) + nt) << 8) + (lane << 3));
                    uint32_t b0, b1;
                    asm volatile("ld.shared.v2.b32 {%0,%1}, [%2];"
                                 : "=r"(b0), "=r"(b1) : "r"(baddr));
                    mma16816(acc[nt], a0, a1, a2, a3, b0, b1);
                }
            }
        }
        // store k+1 into stage s^1
        if (k + 1 < KK) {
            char* ab = smem + AW_OFF(s ^ 1, wid);
            #pragma unroll
            for (int i = 0; i < 8; ++i) {
                int row = i * 2 + (lane >> 4);
                int c = lane & 15;
                *(uint4*)(ab + row * 256 + ((c ^ (row & 7)) << 4)) = ra[i];
            }
            uint4* wd = (uint4*)(smem + WW_OFF(s ^ 1)) + wid * 256 + lane;
            #pragma unroll
            for (int i = 0; i < 8; ++i) wd[i * 32] = rw[i];
        }
        __syncthreads();
    }

    // epilogue: write accumulators + bias
    {
        int gid = lane >> 2, tig = lane & 3;
        const float* bsm = (const float*)(smem + BIAS_OFF);
        size_t r0 = (size_t)(o0 + wid * 16 + gid);
        #pragma unroll
        for (int nt = 0; nt < 16; ++nt) {
            int col = nt * 8 + tig * 2;
            float2 bv = *(const float2*)(bsm + col);
            float2 v0 = make_float2(acc[nt][0] + bv.x, acc[nt][1] + bv.y);
            float2 v1 = make_float2(acc[nt][2] + bv.x, acc[nt][3] + bv.y);
            *(float2*)(out + r0 * CH + col) = v0;
            *(float2*)(out + (r0 + 8) * CH + col) = v1;
        }
    }
}
#endif  // TC_PATH

// ---------------- launch ----------------
extern "C" void kernel_launch(void* const* d_in, const int* in_sizes, int n_in,
                              void* d_out, int out_size) {
    const float* features = (const float*)d_in[0];
    const float* weight   = (const float*)d_in[1];
    const float* bias     = (const float*)d_in[2];
    const int*   in_idx   = (const int*)d_in[3];
    const int*   out_idx  = (const int*)d_in[4];
    float*       out      = (float*)d_out;

    cudaFuncSetAttribute(k_main, cudaFuncAttributeMaxDynamicSharedMemorySize, SMEM_BYTES);

    k_fill<<<(KK * NV + 255) / 256, 256>>>();
    k_scatter<<<(KK * NV + 255) / 256, 256>>>(in_idx, out_idx);
    k_splitf<<<(((NV + 1) * (CH / 2)) + 255) / 256, 256>>>(features);
    k_prepw<<<(KK * CH * CH + 255) / 256, 256>>>(weight);
    k_main<<<NV / 128, 256, SMEM_BYTES>>>(bias, out);
}